// round 8
// baseline (speedup 1.0000x reference)
#include <cuda_runtime.h>
#include <cuda_bf16.h>

#define TT 1024
#define BB 4096
#define TOTAL4 (BB * TT / 4)        // 1048576 float4-groups
#define NBLK 148                    // 1 CTA of 1024 threads per SM (all resident)
#define NEGBIG (-1.0e30f)

// ---- device scratch (static; barrier counter self-manages via sense) ----
__device__ __align__(16) float        g_S[NBLK * 3072];   // [blk][p=3t+c]
__device__ __align__(16) unsigned int g_C[NBLK * 768];    // [blk][3*(t>>2)+c], byte=t&3
__device__ __align__(16) float        g_pS[3072];
__device__ __align__(16) int          g_pN[3072];
__device__ unsigned int          g_count = 0;
__device__ volatile unsigned int g_sense = 0;

// ======================= grid barrier (all CTAs resident) =======================
__device__ __forceinline__ void grid_bar(int tid) {
    __syncthreads();
    if (tid == 0) {
        unsigned int s = g_sense;
        __threadfence();
        if (atomicAdd(&g_count, 1u) == NBLK - 1) {
            g_count = 0;
            __threadfence();
            g_sense = s + 1;
        } else {
            while (g_sense == s) { }
        }
    }
    __syncthreads();
}

// ======================= special functions =======================
__device__ __forceinline__ float stirl_lg(float y) {
    float r  = __fdividef(1.0f, y);
    float L  = __logf(y);
    float r2 = r * r;
    return fmaf(y - 0.5f, L,
                fmaf(r, fmaf(r2, -2.7777778e-3f, 8.3333333e-2f), 0.91893853f - y));
}

__device__ __forceinline__ void stirl_both(float y, float& lg, float& ps) {
    float r  = __fdividef(1.0f, y);
    float L  = __logf(y);
    float r2 = r * r;
    lg = fmaf(y - 0.5f, L,
              fmaf(r, fmaf(r2, -2.7777778e-3f, 8.3333333e-2f), 0.91893853f - y));
    ps = fmaf(-r2, fmaf(-r2, 8.3333333e-3f, 8.3333333e-2f), fmaf(-0.5f, r, L));
}

__device__ __forceinline__ float elem_kl(float l0, float l1, float tw, float tcv) {
    float pw  = __fdividef(1.0f, 1.0f + __expf(-l0));
    float pcs = __fdividef(1.0f, 1.0f + __expf(-l1));
    float pc  = fmaf(pcs, 1023.0f, 5.0f);

    float sp = tcv + 2.0f;
    float sq = pc + 2.0f;
    float ta = fmaf(tcv, tw, 1.0f);
    float tb = sp - ta;
    float pa = fmaf(pc, pw, 1.0f);
    float pb = sq - pa;

    float uta = ta * (ta + 3.0f), Pta = uta * (uta + 2.0f);
    float utb = tb * (tb + 3.0f), Ptb = utb * (utb + 2.0f);
    float upa = pa * (pa + 3.0f), Ppa = upa * (upa + 2.0f);
    float upb = pb * (pb + 3.0f), Ppb = upb * (upb + 2.0f);

    float lgta, psta; stirl_both(ta + 4.0f, lgta, psta);
    float lgtb, pstb; stirl_both(tb + 4.0f, lgtb, pstb);
    float lgsp, pssp; stirl_both(sp,        lgsp, pssp);
    float lgpa = stirl_lg(pa + 4.0f);
    float lgpb = stirl_lg(pb + 4.0f);
    float lgsq = stirl_lg(sq);

    float da = ta - pa, db = tb - pb;
    float Aa  = fmaf(2.0f, uta, 2.0f) * fmaf(2.0f, ta, 3.0f);
    float Ab  = fmaf(2.0f, utb, 2.0f) * fmaf(2.0f, tb, 3.0f);
    float Ptt = Pta * Ptb;
    float corr = __fdividef(fmaf(da * Aa, Ptb, db * Ab * Pta), Ptt);

    float logdiff = __logf(Ptt) - __logf(Ppa * Ppb);

    return (lgpa + lgpb + lgsp) - (lgta + lgtb + lgsq) + logdiff
         + da * psta + db * pstb + (sq - sp) * pssp - corr;
}

// ======================= single fused persistent kernel =======================
__global__ void __launch_bounds__(1024, 1)
fused_kernel(const float* __restrict__ logits, const float* __restrict__ tgt,
             float* __restrict__ out) {
    const int tid = threadIdx.x;
    const int q = tid >> 8, r = tid & 255;
    const int bid = blockIdx.x;
    const float4* tg4 = reinterpret_cast<const float4*>(tgt);
    const float4* lg4 = reinterpret_cast<const float4*>(logits);

    // ---------------- phase 1: per-(t,c) partial sums ----------------
    float s[4][3];
#pragma unroll
    for (int j = 0; j < 4; j++) { s[j][0] = 0.0f; s[j][1] = 0.0f; s[j][2] = 0.0f; }
    unsigned int cn[3] = {0u, 0u, 0u};

#pragma unroll 1
    for (int g = bid * 1024 + tid; g < TOTAL4; g += NBLK * 1024) {
        float4 a = tg4[g * 3 + 0];
        float4 b = tg4[g * 3 + 1];
        float4 c = tg4[g * 3 + 2];
        float4 d = lg4[g * 2 + 0];
        float4 e = lg4[g * 2 + 1];
        float tv[12] = {a.x, a.y, a.z, a.w, b.x, b.y, b.z, b.w, c.x, c.y, c.z, c.w};
        float lv[8]  = {d.x, d.y, d.z, d.w, e.x, e.y, e.z, e.w};
#pragma unroll
        for (int j = 0; j < 4; j++) {
            float x0 = tv[3 * j], x1 = tv[3 * j + 1], x2 = tv[3 * j + 2];
            bool  m  = (x2 > NEGBIG);
            float tw = m ? x0 : 0.5f;
            float tc = m ? x1 : 5.0f;
            int   dx = m ? (int)x2 : -1;
            float kl = elem_kl(lv[2 * j], lv[2 * j + 1], tw, tc);
            s[j][0] += (dx == 0) ? kl : 0.0f;
            s[j][1] += (dx == 1) ? kl : 0.0f;
            s[j][2] += (dx == 2) ? kl : 0.0f;
            cn[0] += (dx == 0) ? (1u << (8 * j)) : 0u;
            cn[1] += (dx == 1) ? (1u << (8 * j)) : 0u;
            cn[2] += (dx == 2) ? (1u << (8 * j)) : 0u;
        }
    }

    // 4-phase fixed-order quarter fold in smem (thread-quarters share t-sets)
    __shared__ float        sh[3072];
    __shared__ unsigned int shc[768];
    if (q == 0) {
#pragma unroll
        for (int j = 0; j < 4; j++)
#pragma unroll
            for (int c = 0; c < 3; c++) sh[12 * r + 3 * j + c] = s[j][c];
#pragma unroll
        for (int c = 0; c < 3; c++) shc[3 * r + c] = cn[c];
    }
    __syncthreads();
#pragma unroll
    for (int qq = 1; qq < 4; qq++) {
        if (q == qq) {
#pragma unroll
            for (int j = 0; j < 4; j++)
#pragma unroll
                for (int c = 0; c < 3; c++) sh[12 * r + 3 * j + c] += s[j][c];
#pragma unroll
            for (int c = 0; c < 3; c++) shc[3 * r + c] += cn[c];
        }
        __syncthreads();
    }
    if (q == 0) {
        const float4* shv = reinterpret_cast<const float4*>(&sh[12 * r]);
        float4* so = reinterpret_cast<float4*>(&g_S[bid * 3072 + 12 * r]);
        so[0] = shv[0]; so[1] = shv[1]; so[2] = shv[2];
        unsigned int* co = &g_C[bid * 768 + 3 * r];
        co[0] = shc[3 * r]; co[1] = shc[3 * r + 1]; co[2] = shc[3 * r + 2];
    }

    grid_bar(tid);

    // ---------------- phase 2: slab reduction (120 one-warp tasks) ----------------
    // task = wid*148 + bid < 120  -> warp 0 of blocks 0..119, one task each.
    {
        const int wid = tid >> 5, l = tid & 31;
        const int task = wid * NBLK + bid;
        if (task < 96) {
            const int p = task * 32 + l;
            float acc = 0.0f;
#pragma unroll 4
            for (int b = 0; b < NBLK; b++)
                acc += __ldcg(&g_S[b * 3072 + p]);        // coalesced, L2-hot
            g_pS[p] = acc;
        } else if (task < 120) {
            const int wi = (task - 96) * 32 + l;          // count word 0..767
            int n[4] = {0, 0, 0, 0};
            int b = 0;
#pragma unroll 1
            for (int chunk = 0; chunk < 17; chunk++) {    // 9*28=252 <= 255: no carry
                unsigned int acc = 0;
#pragma unroll
                for (int i = 0; i < 9; i++) {
                    if (b < NBLK) { acc += __ldcg(&g_C[b * 768 + wi]); b++; }
                }
                n[0] += (int)(acc & 0xFFu);
                n[1] += (int)((acc >> 8) & 0xFFu);
                n[2] += (int)((acc >> 16) & 0xFFu);
                n[3] += (int)(acc >> 24);
            }
            int t4 = wi / 3, c = wi - 3 * t4;             // byte j -> t = 4*t4+j
#pragma unroll
            for (int j = 0; j < 4; j++)
                g_pN[12 * t4 + 3 * j + c] = n[j];         // == 3t+c
        }
    }

    grid_bar(tid);

    // ---------------- phase 3: block 0 folds 1024 per-t terms ----------------
    if (bid != 0) return;
    {
        float acc = 0.0f;
#pragma unroll
        for (int c = 0; c < 3; c++) {
            float S = __ldcg(&g_pS[3 * tid + c]);
            int   N = __ldcg(&g_pN[3 * tid + c]);
            acc += (N > 0) ? __fdividef(S, 3.0f * (float)N) : 0.0f;
        }
#pragma unroll
        for (int off = 16; off > 0; off >>= 1)
            acc += __shfl_xor_sync(0xffffffffu, acc, off);
        __shared__ float ws[32];
        if ((tid & 31) == 0) ws[tid >> 5] = acc;
        __syncthreads();
        if (tid == 0) {
            float tot = 0.0f;
#pragma unroll
            for (int i = 0; i < 32; i++) tot += ws[i];
            out[0] = tot * (1.0f / (float)TT);
        }
    }
}

// ======================= launch =======================
extern "C" void kernel_launch(void* const* d_in, const int* in_sizes, int n_in,
                              void* d_out, int out_size) {
    const float* logits;
    const float* targets;
    if (in_sizes[0] == BB * TT * 2) {          // robust to metadata ordering
        logits  = (const float*)d_in[0];
        targets = (const float*)d_in[1];
    } else {
        logits  = (const float*)d_in[1];
        targets = (const float*)d_in[0];
    }
    float* out = (float*)d_out;

    fused_kernel<<<NBLK, 1024>>>(logits, targets, out);
}

// round 9
// speedup vs baseline: 1.9218x; 1.9218x over previous
#include <cuda_runtime.h>
#include <cuda_bf16.h>

#define TT 1024
#define BB 4096
#define TOTAL4 (BB * TT / 4)        // 1048576 float4-groups
#define NBLK 148                    // 1 CTA of 1024 threads per SM
#define RBLKS 120                   // 96 S-blocks + 24 count-blocks
#define NEGBIG (-1.0e30f)

// ---- device scratch (static; counter self-resets each launch) ----
__device__ __align__(16) float        g_S[NBLK * 3072];   // [blk][p=3t+c]
__device__ __align__(16) unsigned int g_C[NBLK * 768];    // [blk][3*(t>>2)+c], byte=t&3
__device__ __align__(16) float        g_pS[3072];
__device__ __align__(16) int          g_pN[3072];
__device__ unsigned int g_rcnt;

// ======================= special functions =======================
__device__ __forceinline__ float stirl_lg(float y) {
    float r  = __fdividef(1.0f, y);
    float L  = __logf(y);
    float r2 = r * r;
    return fmaf(y - 0.5f, L,
                fmaf(r, fmaf(r2, -2.7777778e-3f, 8.3333333e-2f), 0.91893853f - y));
}

__device__ __forceinline__ void stirl_both(float y, float& lg, float& ps) {
    float r  = __fdividef(1.0f, y);
    float L  = __logf(y);
    float r2 = r * r;
    lg = fmaf(y - 0.5f, L,
              fmaf(r, fmaf(r2, -2.7777778e-3f, 8.3333333e-2f), 0.91893853f - y));
    ps = fmaf(-r2, fmaf(-r2, 8.3333333e-3f, 8.3333333e-2f), fmaf(-0.5f, r, L));
}

__device__ __forceinline__ float elem_kl(float l0, float l1, float tw, float tcv) {
    float pw  = __fdividef(1.0f, 1.0f + __expf(-l0));
    float pcs = __fdividef(1.0f, 1.0f + __expf(-l1));
    float pc  = fmaf(pcs, 1023.0f, 5.0f);

    float sp = tcv + 2.0f;
    float sq = pc + 2.0f;
    float ta = fmaf(tcv, tw, 1.0f);
    float tb = sp - ta;
    float pa = fmaf(pc, pw, 1.0f);
    float pb = sq - pa;

    float uta = ta * (ta + 3.0f), Pta = uta * (uta + 2.0f);
    float utb = tb * (tb + 3.0f), Ptb = utb * (utb + 2.0f);
    float upa = pa * (pa + 3.0f), Ppa = upa * (upa + 2.0f);
    float upb = pb * (pb + 3.0f), Ppb = upb * (upb + 2.0f);

    float lgta, psta; stirl_both(ta + 4.0f, lgta, psta);
    float lgtb, pstb; stirl_both(tb + 4.0f, lgtb, pstb);
    float lgsp, pssp; stirl_both(sp,        lgsp, pssp);
    float lgpa = stirl_lg(pa + 4.0f);
    float lgpb = stirl_lg(pb + 4.0f);
    float lgsq = stirl_lg(sq);

    float da = ta - pa, db = tb - pb;
    float Aa  = fmaf(2.0f, uta, 2.0f) * fmaf(2.0f, ta, 3.0f);
    float Ab  = fmaf(2.0f, utb, 2.0f) * fmaf(2.0f, tb, 3.0f);
    float Ptt = Pta * Ptb;
    float corr = __fdividef(fmaf(da * Aa, Ptb, db * Ab * Pta), Ptt);

    float logdiff = __logf(Ptt) - __logf(Ppa * Ppb);

    return (lgpa + lgpb + lgsp) - (lgta + lgtb + lgsq) + logdiff
         + da * psta + db * pstb + (sq - sp) * pssp - corr;
}

// ======================= kernel 1: main KL pass =======================
// 148 blocks x 1024 threads; warp-uniform skip of fully-padded groups.
__global__ void __launch_bounds__(1024)
main_kernel(const float* __restrict__ logits, const float* __restrict__ tgt) {
    const int tid = threadIdx.x;
    const int q = tid >> 8, r = tid & 255;
    const float4* tg4 = reinterpret_cast<const float4*>(tgt);
    const float4* lg4 = reinterpret_cast<const float4*>(logits);

    float s[4][3];
#pragma unroll
    for (int j = 0; j < 4; j++) { s[j][0] = 0.0f; s[j][1] = 0.0f; s[j][2] = 0.0f; }
    unsigned int cn[3] = {0u, 0u, 0u};

#pragma unroll 1
    for (int g = blockIdx.x * 1024 + tid; g < TOTAL4; g += NBLK * 1024) {
        float4 a = tg4[g * 3 + 0];
        float4 b = tg4[g * 3 + 1];
        float4 c = tg4[g * 3 + 2];
        // class entries for j=0..3: a.z, b.y, c.x, c.w — -inf iff padded
        float mx = fmaxf(fmaxf(a.z, b.y), fmaxf(c.x, c.w));
        if (__any_sync(0xffffffffu, mx > NEGBIG)) {      // warp-uniform
            float4 d = lg4[g * 2 + 0];
            float4 e = lg4[g * 2 + 1];
            float tv[12] = {a.x, a.y, a.z, a.w, b.x, b.y, b.z, b.w, c.x, c.y, c.z, c.w};
            float lv[8]  = {d.x, d.y, d.z, d.w, e.x, e.y, e.z, e.w};
#pragma unroll
            for (int j = 0; j < 4; j++) {
                float x0 = tv[3 * j], x1 = tv[3 * j + 1], x2 = tv[3 * j + 2];
                bool  m  = (x2 > NEGBIG);
                float tw = m ? x0 : 0.5f;
                float tc = m ? x1 : 5.0f;
                int   dx = m ? (int)x2 : -1;
                float kl = elem_kl(lv[2 * j], lv[2 * j + 1], tw, tc);
                s[j][0] += (dx == 0) ? kl : 0.0f;
                s[j][1] += (dx == 1) ? kl : 0.0f;
                s[j][2] += (dx == 2) ? kl : 0.0f;
                cn[0] += (dx == 0) ? (1u << (8 * j)) : 0u;
                cn[1] += (dx == 1) ? (1u << (8 * j)) : 0u;
                cn[2] += (dx == 2) ? (1u << (8 * j)) : 0u;
            }
        }
    }

    // 4-phase fixed-order quarter fold in smem (thread-quarters share t-sets)
    __shared__ float        sh[3072];
    __shared__ unsigned int shc[768];
    if (q == 0) {
#pragma unroll
        for (int j = 0; j < 4; j++)
#pragma unroll
            for (int c = 0; c < 3; c++) sh[12 * r + 3 * j + c] = s[j][c];
#pragma unroll
        for (int c = 0; c < 3; c++) shc[3 * r + c] = cn[c];
    }
    __syncthreads();
#pragma unroll
    for (int qq = 1; qq < 4; qq++) {
        if (q == qq) {
#pragma unroll
            for (int j = 0; j < 4; j++)
#pragma unroll
                for (int c = 0; c < 3; c++) sh[12 * r + 3 * j + c] += s[j][c];
#pragma unroll
            for (int c = 0; c < 3; c++) shc[3 * r + c] += cn[c];
        }
        __syncthreads();
    }

    if (q == 0) {
        const float4* shv = reinterpret_cast<const float4*>(&sh[12 * r]);
        float4* so = reinterpret_cast<float4*>(&g_S[blockIdx.x * 3072 + 12 * r]);
        so[0] = shv[0]; so[1] = shv[1]; so[2] = shv[2];
        unsigned int* co = &g_C[blockIdx.x * 768 + 3 * r];
        co[0] = shc[3 * r]; co[1] = shc[3 * r + 1]; co[2] = shc[3 * r + 2];
    }
}

// ======================= kernel 2: reduce + finalize =======================
__global__ void __launch_bounds__(256)
reduce_kernel(float* __restrict__ out) {
    const int tid = threadIdx.x;
    const int w = tid >> 5, l = tid & 31;
    __shared__ float sS[8][32];
    __shared__ int   sN[8][32][4];

    if (blockIdx.x < 96) {
        const int p = blockIdx.x * 32 + l;
        float acc = 0.0f;
#pragma unroll
        for (int b = w; b < NBLK; b += 8)
            acc += g_S[b * 3072 + p];                    // coalesced per warp
        sS[w][l] = acc;
        __syncthreads();
        if (w == 0) {
            float ssum = 0.0f;
#pragma unroll
            for (int i = 0; i < 8; i++) ssum += sS[i][l];
            g_pS[p] = ssum;
        }
    } else {
        const int wi = (blockIdx.x - 96) * 32 + l;       // count word 0..767
        int n[4] = {0, 0, 0, 0};
        int b = w;
#pragma unroll
        for (int chunk = 0; chunk < 3; chunk++) {        // bytes <= 9*7=63: no carry
            unsigned int acc = 0;
#pragma unroll
            for (int i = 0; i < 9; i++) {
                if (b < NBLK) { acc += g_C[b * 768 + wi]; b += 8; }
            }
            n[0] += (int)(acc & 0xFFu);
            n[1] += (int)((acc >> 8) & 0xFFu);
            n[2] += (int)((acc >> 16) & 0xFFu);
            n[3] += (int)(acc >> 24);
        }
#pragma unroll
        for (int j = 0; j < 4; j++) sN[w][l][j] = n[j];
        __syncthreads();
        if (w == 0) {
            int t4 = wi / 3, c = wi - 3 * t4;            // byte j -> t = 4*t4+j
#pragma unroll
            for (int j = 0; j < 4; j++) {
                int nsum = 0;
#pragma unroll
                for (int i = 0; i < 8; i++) nsum += sN[i][l][j];
                g_pN[12 * t4 + 3 * j + c] = nsum;
            }
        }
    }

    __threadfence();
    __syncthreads();
    __shared__ bool amLast;
    if (tid == 0)
        amLast = (atomicAdd(&g_rcnt, 1u) == (unsigned)(RBLKS - 1));
    __syncthreads();
    if (!amLast) return;
    __threadfence();

    // fold: thread owns t = 4*tid+j; 12 S + 12 N contiguous reads
    const float4* ps4 = reinterpret_cast<const float4*>(&g_pS[12 * tid]);
    const int4*   pn4 = reinterpret_cast<const int4*>(&g_pN[12 * tid]);
    float acc = 0.0f;
#pragma unroll
    for (int k = 0; k < 3; k++) {
        float4 S = ps4[k];
        int4   N = pn4[k];
        acc += (N.x > 0) ? __fdividef(S.x, 3.0f * (float)N.x) : 0.0f;
        acc += (N.y > 0) ? __fdividef(S.y, 3.0f * (float)N.y) : 0.0f;
        acc += (N.z > 0) ? __fdividef(S.z, 3.0f * (float)N.z) : 0.0f;
        acc += (N.w > 0) ? __fdividef(S.w, 3.0f * (float)N.w) : 0.0f;
    }

#pragma unroll
    for (int off = 16; off > 0; off >>= 1)
        acc += __shfl_xor_sync(0xffffffffu, acc, off);
    __shared__ float ws[8];
    if ((tid & 31) == 0) ws[tid >> 5] = acc;
    __syncthreads();
    if (tid == 0) {
        float tot = 0.0f;
#pragma unroll
        for (int i = 0; i < 8; i++) tot += ws[i];
        out[0] = tot * (1.0f / (float)TT);
        g_rcnt = 0;                                      // reset for next replay
    }
}

// ======================= launch =======================
extern "C" void kernel_launch(void* const* d_in, const int* in_sizes, int n_in,
                              void* d_out, int out_size) {
    const float* logits;
    const float* targets;
    if (in_sizes[0] == BB * TT * 2) {
        logits  = (const float*)d_in[0];
        targets = (const float*)d_in[1];
    } else {
        logits  = (const float*)d_in[1];
        targets = (const float*)d_in[0];
    }
    float* out = (float*)d_out;

    main_kernel<<<NBLK, 1024>>>(logits, targets);
    reduce_kernel<<<RBLKS, 256>>>(out);
}

// round 10
// speedup vs baseline: 1.9366x; 1.0077x over previous
#include <cuda_runtime.h>
#include <cuda_bf16.h>

#define TT 1024
#define BB 4096
#define TOTAL4 (BB * TT / 4)        // 1048576 float4-groups
#define NBLK 148                    // 1 CTA of 1024 threads per SM
#define RBLKS 120                   // 96 S-blocks + 24 count-blocks
#define NEGBIG (-1.0e30f)

// ---- device scratch (static; counter self-resets each launch) ----
__device__ __align__(16) float        g_S[NBLK * 3072];   // [blk][p=3t+c]
__device__ __align__(16) unsigned int g_C[NBLK * 768];    // [blk][3*(t>>2)+c], byte=t&3
__device__ __align__(16) float        g_pS[3072];
__device__ __align__(16) int          g_pN[3072];
__device__ unsigned int g_rcnt;

// ======================= special functions =======================
__device__ __forceinline__ float stirl_lg(float y) {
    float r  = __fdividef(1.0f, y);
    float L  = __logf(y);
    float r2 = r * r;
    return fmaf(y - 0.5f, L,
                fmaf(r, fmaf(r2, -2.7777778e-3f, 8.3333333e-2f), 0.91893853f - y));
}

__device__ __forceinline__ void stirl_both(float y, float& lg, float& ps) {
    float r  = __fdividef(1.0f, y);
    float L  = __logf(y);
    float r2 = r * r;
    lg = fmaf(y - 0.5f, L,
              fmaf(r, fmaf(r2, -2.7777778e-3f, 8.3333333e-2f), 0.91893853f - y));
    ps = fmaf(-r2, fmaf(-r2, 8.3333333e-3f, 8.3333333e-2f), fmaf(-0.5f, r, L));
}

__device__ __forceinline__ float elem_kl(float l0, float l1, float tw, float tcv) {
    float pw  = __fdividef(1.0f, 1.0f + __expf(-l0));
    float pcs = __fdividef(1.0f, 1.0f + __expf(-l1));
    float pc  = fmaf(pcs, 1023.0f, 5.0f);

    float sp = tcv + 2.0f;
    float sq = pc + 2.0f;
    float ta = fmaf(tcv, tw, 1.0f);
    float tb = sp - ta;
    float pa = fmaf(pc, pw, 1.0f);
    float pb = sq - pa;

    float uta = ta * (ta + 3.0f), Pta = uta * (uta + 2.0f);
    float utb = tb * (tb + 3.0f), Ptb = utb * (utb + 2.0f);
    float upa = pa * (pa + 3.0f), Ppa = upa * (upa + 2.0f);
    float upb = pb * (pb + 3.0f), Ppb = upb * (upb + 2.0f);

    float lgta, psta; stirl_both(ta + 4.0f, lgta, psta);
    float lgtb, pstb; stirl_both(tb + 4.0f, lgtb, pstb);
    float lgsp, pssp; stirl_both(sp,        lgsp, pssp);
    float lgpa = stirl_lg(pa + 4.0f);
    float lgpb = stirl_lg(pb + 4.0f);
    float lgsq = stirl_lg(sq);

    float da = ta - pa, db = tb - pb;
    float Aa  = fmaf(2.0f, uta, 2.0f) * fmaf(2.0f, ta, 3.0f);
    float Ab  = fmaf(2.0f, utb, 2.0f) * fmaf(2.0f, tb, 3.0f);
    float Ptt = Pta * Ptb;
    float corr = __fdividef(fmaf(da * Aa, Ptb, db * Ab * Pta), Ptt);

    float logdiff = __logf(Ptt) - __logf(Ppa * Ppb);

    return (lgpa + lgpb + lgsp) - (lgta + lgtb + lgsq) + logdiff
         + da * psta + db * pstb + (sq - sp) * pssp - corr;
}

// ======================= kernel 1: main KL pass =======================
// 148 blocks x 1024 threads. ALL loads hoisted (MLP=5); warp-uniform compute skip.
__global__ void __launch_bounds__(1024)
main_kernel(const float* __restrict__ logits, const float* __restrict__ tgt) {
    const int tid = threadIdx.x;
    const int q = tid >> 8, r = tid & 255;
    const float4* tg4 = reinterpret_cast<const float4*>(tgt);
    const float4* lg4 = reinterpret_cast<const float4*>(logits);

    float s[4][3];
#pragma unroll
    for (int j = 0; j < 4; j++) { s[j][0] = 0.0f; s[j][1] = 0.0f; s[j][2] = 0.0f; }
    unsigned int cn[3] = {0u, 0u, 0u};

#pragma unroll 1
    for (int g = blockIdx.x * 1024 + tid; g < TOTAL4; g += NBLK * 1024) {
        // unconditional front-batched loads (keep MLP high)
        float4 a = tg4[g * 3 + 0];
        float4 b = tg4[g * 3 + 1];
        float4 c = tg4[g * 3 + 2];
        float4 d = lg4[g * 2 + 0];
        float4 e = lg4[g * 2 + 1];
        // class entries for j=0..3: a.z, b.y, c.x, c.w — -inf iff padded
        float mx = fmaxf(fmaxf(a.z, b.y), fmaxf(c.x, c.w));
        if (__any_sync(0xffffffffu, mx > NEGBIG)) {      // warp-uniform compute skip
            float tv[12] = {a.x, a.y, a.z, a.w, b.x, b.y, b.z, b.w, c.x, c.y, c.z, c.w};
            float lv[8]  = {d.x, d.y, d.z, d.w, e.x, e.y, e.z, e.w};
#pragma unroll
            for (int j = 0; j < 4; j++) {
                float x0 = tv[3 * j], x1 = tv[3 * j + 1], x2 = tv[3 * j + 2];
                bool  m  = (x2 > NEGBIG);
                float tw = m ? x0 : 0.5f;
                float tc = m ? x1 : 5.0f;
                int   dx = m ? (int)x2 : -1;
                float kl = elem_kl(lv[2 * j], lv[2 * j + 1], tw, tc);
                // predicated accumulate (no SEL+ADD pairs)
                if (dx == 0) { s[j][0] += kl; cn[0] += (1u << (8 * j)); }
                if (dx == 1) { s[j][1] += kl; cn[1] += (1u << (8 * j)); }
                if (dx == 2) { s[j][2] += kl; cn[2] += (1u << (8 * j)); }
            }
        }
    }

    // 4-phase fixed-order quarter fold in smem (thread-quarters share t-sets)
    __shared__ float        sh[3072];
    __shared__ unsigned int shc[768];
    if (q == 0) {
#pragma unroll
        for (int j = 0; j < 4; j++)
#pragma unroll
            for (int c = 0; c < 3; c++) sh[12 * r + 3 * j + c] = s[j][c];
#pragma unroll
        for (int c = 0; c < 3; c++) shc[3 * r + c] = cn[c];
    }
    __syncthreads();
#pragma unroll
    for (int qq = 1; qq < 4; qq++) {
        if (q == qq) {
#pragma unroll
            for (int j = 0; j < 4; j++)
#pragma unroll
                for (int c = 0; c < 3; c++) sh[12 * r + 3 * j + c] += s[j][c];
#pragma unroll
            for (int c = 0; c < 3; c++) shc[3 * r + c] += cn[c];
        }
        __syncthreads();
    }

    if (q == 0) {
        const float4* shv = reinterpret_cast<const float4*>(&sh[12 * r]);
        float4* so = reinterpret_cast<float4*>(&g_S[blockIdx.x * 3072 + 12 * r]);
        so[0] = shv[0]; so[1] = shv[1]; so[2] = shv[2];
        unsigned int* co = &g_C[blockIdx.x * 768 + 3 * r];
        co[0] = shc[3 * r]; co[1] = shc[3 * r + 1]; co[2] = shc[3 * r + 2];
    }
}

// ======================= kernel 2: reduce + finalize =======================
__global__ void __launch_bounds__(256)
reduce_kernel(float* __restrict__ out) {
    const int tid = threadIdx.x;
    const int w = tid >> 5, l = tid & 31;
    __shared__ float sS[8][32];
    __shared__ int   sN[8][32][4];

    if (blockIdx.x < 96) {
        const int p = blockIdx.x * 32 + l;
        float acc = 0.0f;
#pragma unroll
        for (int b = w; b < NBLK; b += 8)
            acc += g_S[b * 3072 + p];                    // coalesced per warp
        sS[w][l] = acc;
        __syncthreads();
        if (w == 0) {
            float ssum = 0.0f;
#pragma unroll
            for (int i = 0; i < 8; i++) ssum += sS[i][l];
            g_pS[p] = ssum;
        }
    } else {
        const int wi = (blockIdx.x - 96) * 32 + l;       // count word 0..767
        int n[4] = {0, 0, 0, 0};
        int b = w;
#pragma unroll
        for (int chunk = 0; chunk < 3; chunk++) {        // bytes <= 9*7=63: no carry
            unsigned int acc = 0;
#pragma unroll
            for (int i = 0; i < 9; i++) {
                if (b < NBLK) { acc += g_C[b * 768 + wi]; b += 8; }
            }
            n[0] += (int)(acc & 0xFFu);
            n[1] += (int)((acc >> 8) & 0xFFu);
            n[2] += (int)((acc >> 16) & 0xFFu);
            n[3] += (int)(acc >> 24);
        }
#pragma unroll
        for (int j = 0; j < 4; j++) sN[w][l][j] = n[j];
        __syncthreads();
        if (w == 0) {
            int t4 = wi / 3, c = wi - 3 * t4;            // byte j -> t = 4*t4+j
#pragma unroll
            for (int j = 0; j < 4; j++) {
                int nsum = 0;
#pragma unroll
                for (int i = 0; i < 8; i++) nsum += sN[i][l][j];
                g_pN[12 * t4 + 3 * j + c] = nsum;
            }
        }
    }

    __threadfence();
    __syncthreads();
    __shared__ bool amLast;
    if (tid == 0)
        amLast = (atomicAdd(&g_rcnt, 1u) == (unsigned)(RBLKS - 1));
    __syncthreads();
    if (!amLast) return;
    __threadfence();

    // fold: thread owns t = 4*tid+j; 12 S + 12 N contiguous reads
    const float4* ps4 = reinterpret_cast<const float4*>(&g_pS[12 * tid]);
    const int4*   pn4 = reinterpret_cast<const int4*>(&g_pN[12 * tid]);
    float acc = 0.0f;
#pragma unroll
    for (int k = 0; k < 3; k++) {
        float4 S = ps4[k];
        int4   N = pn4[k];
        acc += (N.x > 0) ? __fdividef(S.x, 3.0f * (float)N.x) : 0.0f;
        acc += (N.y > 0) ? __fdividef(S.y, 3.0f * (float)N.y) : 0.0f;
        acc += (N.z > 0) ? __fdividef(S.z, 3.0f * (float)N.z) : 0.0f;
        acc += (N.w > 0) ? __fdividef(S.w, 3.0f * (float)N.w) : 0.0f;
    }

#pragma unroll
    for (int off = 16; off > 0; off >>= 1)
        acc += __shfl_xor_sync(0xffffffffu, acc, off);
    __shared__ float ws[8];
    if ((tid & 31) == 0) ws[tid >> 5] = acc;
    __syncthreads();
    if (tid == 0) {
        float tot = 0.0f;
#pragma unroll
        for (int i = 0; i < 8; i++) tot += ws[i];
        out[0] = tot * (1.0f / (float)TT);
        g_rcnt = 0;                                      // reset for next replay
    }
}

// ======================= launch =======================
extern "C" void kernel_launch(void* const* d_in, const int* in_sizes, int n_in,
                              void* d_out, int out_size) {
    const float* logits;
    const float* targets;
    if (in_sizes[0] == BB * TT * 2) {
        logits  = (const float*)d_in[0];
        targets = (const float*)d_in[1];
    } else {
        logits  = (const float*)d_in[1];
        targets = (const float*)d_in[0];
    }
    float* out = (float*)d_out;

    main_kernel<<<NBLK, 1024>>>(logits, targets);
    reduce_kernel<<<RBLKS, 256>>>(out);
}